// round 1
// baseline (speedup 1.0000x reference)
#include <cuda_runtime.h>
#include <cuda_bf16.h>
#include <stdint.h>

// PseudoOneHotEncoding: out[b, l, c] = table[seq[b, l], c]
//   seq:   [128, 8192] int32   (1,048,576 tokens)
//   table: [27, 21]    float32 (567 elements)
//   out:   [128, 8192, 21] float32 (22,020,096 elements, divisible by 4)
//
// Strategy: flat float4 store layout. Each thread produces one float4 of the
// flattened output. token = idx/21 computed once, then increment-with-wrap.
// Table staged in shared memory; seq loads hit L1 (21x reuse per token).

#define TABLE_ELEMS (27 * 21)
#define TPB 256

__global__ __launch_bounds__(TPB)
void pseudo_onehot_kernel(const int* __restrict__ seq,
                          const float* __restrict__ table,
                          float4* __restrict__ out,
                          unsigned n4)
{
    __shared__ float tab[TABLE_ELEMS];
    #pragma unroll
    for (int i = threadIdx.x; i < TABLE_ELEMS; i += TPB)
        tab[i] = table[i];
    __syncthreads();

    unsigned i = blockIdx.x * TPB + threadIdx.x;
    if (i >= n4) return;

    unsigned base = 4u * i;
    // token = base / 21, col = base % 21 (compiler emits umulhi for const 21)
    unsigned tok = base / 21u;
    unsigned col = base - tok * 21u;
    int s = __ldg(&seq[tok]);

    float v0, v1, v2, v3;

    v0 = tab[(unsigned)s * 21u + col];
    if (++col == 21u) { col = 0u; s = __ldg(&seq[++tok]); }

    v1 = tab[(unsigned)s * 21u + col];
    if (++col == 21u) { col = 0u; s = __ldg(&seq[++tok]); }

    v2 = tab[(unsigned)s * 21u + col];
    if (++col == 21u) { col = 0u; s = __ldg(&seq[++tok]); }

    v3 = tab[(unsigned)s * 21u + col];
    // no wrap update after the last element (would read seq one past the end)

    out[i] = make_float4(v0, v1, v2, v3);
}

extern "C" void kernel_launch(void* const* d_in, const int* in_sizes, int n_in,
                              void* d_out, int out_size)
{
    const int*   seq   = (const int*)d_in[0];    // [128*8192] int32
    const float* table = (const float*)d_in[1];  // [27*21] float32
    float4*      out   = (float4*)d_out;

    unsigned n4 = (unsigned)(out_size / 4);      // out_size divisible by 4
    unsigned grid = (n4 + TPB - 1) / TPB;

    pseudo_onehot_kernel<<<grid, TPB>>>(seq, table, out, n4);
}